// round 10
// baseline (speedup 1.0000x reference)
#include <cuda_runtime.h>

#define TT 4096
#define BB 32
#define DD 128
#define D3 384
#define NSTAGE 16
#define NSCAN 64   // 2 CTAs per batch element

// Scratch for xi = x @ Wi + bi : [T, B, 3D] fp32 = 201 MB.
__device__ float g_xi[(size_t)TT * BB * D3];
__device__ int g_reset_mode;  // 0 = int32, 1 = float32, 2 = uint8/bool
__device__ int g_ready[TT];   // per-timestep xi completion flags

// ---------------------------------------------------------------------------
// Helpers
// ---------------------------------------------------------------------------
__device__ __forceinline__ int read_reset(const void* r, int idx, int mode) {
    if (mode == 0) return ((const int*)r)[idx] != 0;
    if (mode == 1) return ((const float*)r)[idx] != 0.0f;
    return ((const unsigned char*)r)[idx] != 0;
}

__device__ __forceinline__ unsigned long long pack2(float lo, float hi) {
    unsigned long long p;
    asm("mov.b64 %0, {%1, %2};" : "=l"(p) : "f"(lo), "f"(hi));
    return p;
}

__device__ __forceinline__ void fma2(unsigned long long& acc,
                                     unsigned long long a,
                                     unsigned long long b) {
    asm("fma.rn.f32x2 %0, %1, %2, %0;" : "+l"(acc) : "l"(a), "l"(b));
}

__device__ __forceinline__ unsigned long long add2(unsigned long long a,
                                                   unsigned long long b) {
    unsigned long long r;
    asm("add.rn.f32x2 %0, %1, %2;" : "=l"(r) : "l"(a), "l"(b));
    return r;
}

__device__ __forceinline__ float hsum2(unsigned long long a) {
    float lo, hi;
    asm("mov.b64 {%0, %1}, %2;" : "=f"(lo), "=f"(hi) : "l"(a));
    return lo + hi;
}

__device__ __forceinline__ void cp_async16(void* smem_dst, const void* gmem_src) {
    unsigned s = (unsigned)__cvta_generic_to_shared(smem_dst);
    asm volatile("cp.async.cg.shared.global [%0], [%1], 16;"
                 :: "r"(s), "l"(gmem_src) : "memory");
}

__device__ __forceinline__ int ld_acq(const int* p) {
    int v;
    asm volatile("ld.acquire.gpu.b32 %0, [%1];" : "=r"(v) : "l"(p) : "memory");
    return v;
}

__device__ __forceinline__ void st_rel(int* p, int v) {
    asm volatile("st.release.gpu.b32 [%0], %1;" :: "l"(p), "r"(v) : "memory");
}

__device__ __forceinline__ unsigned smem_u32(const void* p) {
    return (unsigned)__cvta_generic_to_shared(p);
}

__device__ __forceinline__ unsigned mapa_peer(unsigned addr, unsigned rank) {
    unsigned r;
    asm("mapa.shared::cluster.u32 %0, %1, %2;" : "=r"(r) : "r"(addr), "r"(rank));
    return r;
}

__device__ __forceinline__ void dsmem_st_f32(unsigned addr, float v) {
    asm volatile("st.shared::cluster.f32 [%0], %1;" :: "r"(addr), "f"(v) : "memory");
}

__device__ __forceinline__ void mbar_arrive_cluster(unsigned addr) {
    asm volatile("mbarrier.arrive.release.cluster.shared::cluster.b64 _, [%0];"
                 :: "r"(addr) : "memory");
}

__device__ __forceinline__ void mbar_wait_cluster(unsigned addr, int parity) {
    unsigned done;
    asm volatile(
        "{\n\t.reg .pred p;\n\t"
        "mbarrier.try_wait.parity.acquire.cluster.shared::cta.b64 p, [%1], %2;\n\t"
        "selp.b32 %0, 1, 0, p;\n\t}"
        : "=r"(done) : "r"(addr), "r"((unsigned)parity) : "memory");
    if (!done) {
        asm volatile(
            "{\n\t.reg .pred P1;\n\t"
            "W_%=:\n\t"
            "mbarrier.try_wait.parity.acquire.cluster.shared::cta.b64 P1, [%0], %1;\n\t"
            "@P1 bra.uni D_%=;\n\t"
            "bra.uni W_%=;\n\t"
            "D_%=:\n\t}"
            :: "r"(addr), "r"((unsigned)parity) : "memory");
    }
}

// ---------------------------------------------------------------------------
// Probe resets dtype + clear ready flags for this replay.
// ---------------------------------------------------------------------------
__global__ void probe_clear_kernel(const unsigned int* __restrict__ r) {
    for (int i = threadIdx.x; i < TT; i += blockDim.x) g_ready[i] = 0;
    __shared__ int s_not01, s_notf;
    if (threadIdx.x == 0) { s_not01 = 0; s_notf = 0; }
    __syncthreads();
    int not01 = 0, notf = 0;
    for (int i = threadIdx.x; i < 32768; i += blockDim.x) {
        unsigned v = r[i];
        if (v != 0u && v != 1u) not01 = 1;
        if (v != 0u && v != 0x3F800000u) notf = 1;
    }
    if (not01) atomicOr(&s_not01, 1);
    if (notf)  atomicOr(&s_notf, 1);
    __syncthreads();
    if (threadIdx.x == 0)
        g_reset_mode = (!s_not01) ? 0 : ((!s_notf) ? 1 : 2);
}

// ---------------------------------------------------------------------------
// GEMM role: blocks NSCAN..grid-1. Block gb owns timesteps t = gb + k*ngemm.
// ---------------------------------------------------------------------------
__device__ __forceinline__ void gemm_role(const float* __restrict__ x,
                                          const float* __restrict__ Wi,
                                          const float* __restrict__ bi,
                                          int gb, int ngemm) {
    __shared__ __align__(16) float xs[2][DD];
    const int j = threadIdx.x;

    unsigned long long w2[64];
#pragma unroll
    for (int k = 0; k < 64; k++)
        w2[k] = pack2(Wi[(2 * k) * D3 + j], Wi[(2 * k + 1) * D3 + j]);
    const float bj = bi[j];

    for (int t = gb; t < TT; t += ngemm) {
        const int r0 = t * BB;
        for (int rp = 0; rp < BB; rp += 2) {
            const int r = r0 + rp;
            if (j < 256)
                xs[j >> 7][j & 127] = x[(size_t)(r + (j >> 7)) * DD + (j & 127)];
            __syncthreads();

            unsigned long long a00 = 0ull, a01 = 0ull, a10 = 0ull, a11 = 0ull;
            const ulonglong2* x0 = (const ulonglong2*)xs[0];
            const ulonglong2* x1 = (const ulonglong2*)xs[1];
#pragma unroll
            for (int k = 0; k < 32; k++) {
                ulonglong2 v0 = x0[k];
                ulonglong2 v1 = x1[k];
                fma2(a00, w2[2 * k],     v0.x);
                fma2(a01, w2[2 * k + 1], v0.y);
                fma2(a10, w2[2 * k],     v1.x);
                fma2(a11, w2[2 * k + 1], v1.y);
            }
            g_xi[(size_t)r * D3 + j]       = bj + hsum2(add2(a00, a01));
            g_xi[(size_t)(r + 1) * D3 + j] = bj + hsum2(add2(a10, a11));
            __syncthreads();
        }
        __threadfence();
        __syncthreads();
        if (j == 0) st_rel(&g_ready[t], 1);
    }
}

// ---------------------------------------------------------------------------
// Scan role: 2 CTAs (a cluster pair) per batch element.
// CTA `half` owns the 192 Wh columns with (col mod 128) in [64*half, 64*half+64)
// => it computes gates and new h for d in [64*half, 64*half+64) locally.
// Split-k: thread j (cl = j%192, kr = j/192) accumulates 64 k-values of
// column(cl): kr==0 -> the CTA-local k half [64*half,...), kr==1 -> remote.
// Per step: [remote threads: mbar wait] -> 64-k dot -> partial[] -> B1 ->
// gate(0-63) / ys(64-127) / refill(192-287) -> B2. New h crosses CTAs via
// DSMEM store + mbarrier (phase pair, release/acquire cluster scope).
// ---------------------------------------------------------------------------
__device__ __forceinline__ void scan_role(const void* __restrict__ resets,
                                          const float* __restrict__ Wh,
                                          const float* __restrict__ bhn,
                                          float* __restrict__ ys,
                                          int b, int half) {
    __shared__ __align__(16) float h[2][DD];
    __shared__ float part[D3];
    __shared__ __align__(16) float xstage[NSTAGE][D3];
    __shared__ unsigned char srst[TT];
    __shared__ __align__(8) unsigned long long mbar[2];

    const int j  = threadIdx.x;
    const int cl = j % 192;            // column-local index 0..191
    const int kr = j / 192;            // 0 = local k-half, 1 = remote k-half
    const int col = 128 * (cl >> 6) + 64 * half + (cl & 63);
    const int k0  = (kr == 0) ? 64 * half : 64 * (1 - half);
    const int mode = g_reset_mode;

    const bool is_gate = (j < 64);
    const bool is_ys   = (j >= 64 && j < 128);
    const bool is_refl = (j >= 192 && j < 288);
    const int  rl      = j - 192;      // refill lane 0..95

    // 64-length column slice of Wh, packed in 32 f32x2 pairs.
    unsigned long long w2[32];
#pragma unroll
    for (int k = 0; k < 32; k++)
        w2[k] = pack2(Wh[(k0 + 2 * k) * D3 + col], Wh[(k0 + 2 * k + 1) * D3 + col]);
    const float bn = is_gate ? bhn[64 * half + j] : 0.0f;

    if (j < DD) h[0][j] = 0.0f;        // both CTAs zero the FULL h vector

    for (int t = j; t < TT; t += 384)
        srst[t] = (unsigned char)read_reset(resets, t * BB + b, mode);

    if (j == 0) {
        asm volatile("mbarrier.init.shared.b64 [%0], 64;" :: "r"(smem_u32(&mbar[0])) : "memory");
        asm volatile("mbarrier.init.shared.b64 [%0], 64;" :: "r"(smem_u32(&mbar[1])) : "memory");
        asm volatile("fence.mbarrier_init.release.cluster;" ::: "memory");
    }
    __syncthreads();
    // Both CTAs' mbarriers must be live before any cross-CTA arrive.
    asm volatile("barrier.cluster.arrive.aligned;" ::: "memory");
    asm volatile("barrier.cluster.wait.aligned;" ::: "memory");

    // Peer addresses (offset arithmetic stays inside the peer aperture).
    const unsigned peer = (unsigned)(half ^ 1);
    const unsigned peer_h0   = mapa_peer(smem_u32(&h[0][0]), peer);
    const unsigned peer_h1   = mapa_peer(smem_u32(&h[1][0]), peer);
    const unsigned peer_mbar = mapa_peer(smem_u32(&mbar[0]), peer);
    const unsigned my_mbar   = smem_u32(&mbar[0]);

    // Prime the xi ring (refill threads own all cp.async group state).
    if (is_refl) {
        for (int s = 0; s < NSTAGE; s++) {
            while (ld_acq(&g_ready[s]) == 0) __nanosleep(64);
            cp_async16(&xstage[s][rl * 4],
                       g_xi + ((size_t)s * BB + b) * D3 + rl * 4);
            asm volatile("cp.async.commit_group;" ::: "memory");
        }
        asm volatile("cp.async.wait_group %0;" :: "n"(NSTAGE - 1) : "memory");
    }
    __syncthreads();

    float* yp = is_ys ? (ys + (size_t)b * DD + 64 * half + (j - 64)) : ys;
    const float* rp = g_xi + ((size_t)NSTAGE * BB + b) * D3 + rl * 4;

    int F = NSTAGE;
    int ph0 = 0, ph1 = 0;
    int p = 0;
    for (int t = 0; t < TT; t++) {
        const int st = t & (NSTAGE - 1);

        // Gate threads preload xi + reset flag before the dot (so refill may
        // overwrite slot st after B1).
        float xr = 0.0f, xz = 0.0f, xn = 0.0f;
        int rst = 0;
        if (is_gate) {
            const float* xi_s = xstage[st];
            xr = xi_s[64 * half + j];
            xz = xi_s[128 + 64 * half + j];
            xn = xi_s[256 + 64 * half + j];
            rst = srst[t];
        }

        // Remote-k threads wait for the peer's h contribution of step t.
        if (kr && t > 0) {
            const int idx = t & 1;
            const int par = idx ? ph1 : ph0;
            mbar_wait_cluster(my_mbar + idx * 8, par);
            if (idx) ph1 ^= 1; else ph0 ^= 1;
        }

        // 64-length partial dot over this thread's k-range.
        unsigned long long a0 = 0ull, a1 = 0ull, a2 = 0ull, a3 = 0ull;
        const ulonglong2* h2 = (const ulonglong2*)&h[p][k0];
#pragma unroll
        for (int k = 0; k < 8; k++) {
            ulonglong2 va = h2[2 * k];
            ulonglong2 vb = h2[2 * k + 1];
            fma2(a0, w2[4 * k + 0], va.x);
            fma2(a1, w2[4 * k + 1], va.y);
            fma2(a2, w2[4 * k + 2], vb.x);
            fma2(a3, w2[4 * k + 3], vb.y);
        }
        part[j] = hsum2(add2(add2(a0, a1), add2(a2, a3)));
        __syncthreads();  // B1: partials published; slot-st reads done.

        if (is_gate) {
            const int d = 64 * half + j;
            float hr = rst ? 0.0f : (part[j]       + part[j + 192]);
            float hz = rst ? 0.0f : (part[64 + j]  + part[256 + j]);
            float hn = rst ? 0.0f : (part[128 + j] + part[320 + j]);
            float sn = hn + bn;
            float rg = __fdividef(1.0f, 1.0f + __expf(-(xr + hr)));
            float zg = __fdividef(1.0f, 1.0f + __expf(-(xz + hz)));
            float ar = xn + rg * sn;
            float ng = __fdividef(2.0f, 1.0f + __expf(-2.0f * ar)) - 1.0f;
            float hp = rst ? 0.0f : h[p][d];
            float nh = (1.0f - zg) * ng + zg * hp;
            h[p ^ 1][d] = nh;
            // Push to peer + arrive on peer's barrier for step t+1.
            unsigned ph = ((p ^ 1) ? peer_h1 : peer_h0) + d * 4;
            dsmem_st_f32(ph, nh);
            mbar_arrive_cluster(peer_mbar + ((t + 1) & 1) * 8);
        } else if (is_ys) {
            if (t > 0) {                 // h[p] holds step t-1's output
                *yp = h[p][64 * half + (j - 64)];
                yp += BB * DD;
            }
        } else if (is_refl) {
            const int need = t + NSTAGE;
            if (need < TT) {
                if (need >= F) {
                    int probe_t = need + 256;
                    if (probe_t > TT - 1) probe_t = TT - 1;
                    if (ld_acq(&g_ready[probe_t])) {
                        F = probe_t + 1;
                    } else {
                        while (ld_acq(&g_ready[need]) == 0) __nanosleep(64);
                        F = need + 1;
                    }
                }
                cp_async16(&xstage[st][rl * 4], rp);
            }
            rp += (size_t)BB * D3;
            asm volatile("cp.async.commit_group;" ::: "memory");
            asm volatile("cp.async.wait_group %0;" :: "n"(NSTAGE - 1) : "memory");
        }
        __syncthreads();  // B2: local h half published.

        p ^= 1;
    }

    if (is_ys) *yp = h[p][64 * half + (j - 64)];  // row TT-1

    // Peer may still be DSMEM-writing into this CTA's smem — don't exit early.
    asm volatile("barrier.cluster.arrive.aligned;" ::: "memory");
    asm volatile("barrier.cluster.wait.aligned;" ::: "memory");
}

// ---------------------------------------------------------------------------
// Fused kernel, cluster (2,1,1). Blocks 0..63: scan pairs (batch b = blk/2,
// half = blk&1; cluster pairs align since 64 is even). Blocks 64..: GEMM
// (their clusters never use DSMEM/cluster barriers). >=128 regs/thread ->
// 1 CTA/SM; grid == #SMs (even) => all CTAs resident, no deadlock.
// ---------------------------------------------------------------------------
__global__ void __cluster_dims__(2, 1, 1) __launch_bounds__(384, 1)
fused_kernel(const float* __restrict__ x,
             const void* __restrict__ resets,
             const float* __restrict__ Wi,
             const float* __restrict__ bi,
             const float* __restrict__ Wh,
             const float* __restrict__ bhn,
             float* __restrict__ ys,
             int ngemm) {
    if (blockIdx.x < NSCAN)
        scan_role(resets, Wh, bhn, ys, blockIdx.x >> 1, blockIdx.x & 1);
    else
        gemm_role(x, Wi, bi, (int)blockIdx.x - NSCAN, ngemm);
}

// ---------------------------------------------------------------------------
extern "C" void kernel_launch(void* const* d_in, const int* in_sizes, int n_in,
                              void* d_out, int out_size) {
    const float* x      = (const float*)d_in[0];
    const void*  resets = d_in[1];
    const float* Wi     = (const float*)d_in[2];
    const float* bi     = (const float*)d_in[3];
    const float* Wh     = (const float*)d_in[4];
    const float* bhn    = (const float*)d_in[5];
    float* ys = (float*)d_out;

    int dev = 0, nsm = 148;
    cudaGetDevice(&dev);
    cudaDeviceGetAttribute(&nsm, cudaDevAttrMultiProcessorCount, dev);
    nsm &= ~1;                       // cluster size 2 divides the grid
    if (nsm < NSCAN + 2) nsm = NSCAN + 2;

    probe_clear_kernel<<<1, 256>>>((const unsigned int*)resets);
    fused_kernel<<<nsm, 384>>>(x, resets, Wi, bi, Wh, bhn, ys, nsm - NSCAN);
}